// round 1
// baseline (speedup 1.0000x reference)
#include <cuda_runtime.h>
#include <math.h>

// ---------------- scratch (no allocations allowed) ----------------
// Fm/Gm/Hm: [4][512][4096], attn: [4][4096][4096], meanT/stdT: [4][512][4096]
__device__ float g_Fm[4u * 512u * 4096u];
__device__ float g_Gm[4u * 512u * 4096u];
__device__ float g_Hm[4u * 512u * 4096u];
__device__ float g_attn[4ull * 4096ull * 4096ull];
__device__ float g_meanT[4u * 512u * 4096u];
__device__ float g_stdT[4u * 512u * 4096u];

#define BK 8

// ---------------- block reductions ----------------
__device__ __forceinline__ float block_reduce_max(float v, float* red) {
    #pragma unroll
    for (int o = 16; o > 0; o >>= 1) v = fmaxf(v, __shfl_xor_sync(0xffffffffu, v, o));
    int wid = threadIdx.x >> 5, lid = threadIdx.x & 31;
    if (lid == 0) red[wid] = v;
    __syncthreads();
    if (wid == 0) {
        v = (lid < 8) ? red[lid] : -1e30f;
        #pragma unroll
        for (int o = 4; o > 0; o >>= 1) v = fmaxf(v, __shfl_xor_sync(0xffffffffu, v, o));
        if (lid == 0) red[0] = v;
    }
    __syncthreads();
    float r = red[0];
    __syncthreads();
    return r;
}

__device__ __forceinline__ float block_reduce_sum(float v, float* red) {
    #pragma unroll
    for (int o = 16; o > 0; o >>= 1) v += __shfl_xor_sync(0xffffffffu, v, o);
    int wid = threadIdx.x >> 5, lid = threadIdx.x & 31;
    if (lid == 0) red[wid] = v;
    __syncthreads();
    if (wid == 0) {
        v = (lid < 8) ? red[lid] : 0.f;
        #pragma unroll
        for (int o = 4; o > 0; o >>= 1) v += __shfl_xor_sync(0xffffffffu, v, o);
        if (lid == 0) red[0] = v;
    }
    __syncthreads();
    float r = red[0];
    __syncthreads();
    return r;
}

// ---------------- GEMM 1: conv1x1  Y[b][m][n] = sum_k W[m][k] * X[b][k][n] + bias[m]
// M=512, N=4096, K=512. Tile 128x128xBK, 256 threads, 8x8 micro.
__global__ __launch_bounds__(256) void gemm_conv(
    const float* __restrict__ W, const float* __restrict__ X,
    const float* __restrict__ bias, float* __restrict__ Y,
    int M, int N, int K)
{
    int b = blockIdx.z;
    const float* Xb = X + (size_t)b * K * N;
    float* Yb = Y + (size_t)b * M * N;
    int n0 = blockIdx.x * 128;
    int m0 = blockIdx.y * 128;

    __shared__ float As[BK][128];
    __shared__ float Bs[BK][128];

    int tid = threadIdx.x;
    int a_row = tid >> 1;            // 0..127 (m)
    int a_col = (tid & 1) * 4;       // 0 or 4 (k)
    int b_row = tid >> 5;            // 0..7   (k)
    int b_col = (tid & 31) * 4;      // 0..124 (n)
    int ty = tid >> 4, tx = tid & 15;

    float acc[8][8];
    #pragma unroll
    for (int i = 0; i < 8; i++)
        #pragma unroll
        for (int j = 0; j < 8; j++) acc[i][j] = 0.f;

    for (int k0 = 0; k0 < K; k0 += BK) {
        float4 av = *(const float4*)(W + (size_t)(m0 + a_row) * K + k0 + a_col);
        As[a_col + 0][a_row] = av.x;
        As[a_col + 1][a_row] = av.y;
        As[a_col + 2][a_row] = av.z;
        As[a_col + 3][a_row] = av.w;
        *(float4*)(&Bs[b_row][b_col]) =
            *(const float4*)(Xb + (size_t)(k0 + b_row) * N + n0 + b_col);
        __syncthreads();
        #pragma unroll
        for (int kk = 0; kk < BK; kk++) {
            float a[8], bf[8];
            *(float4*)(a)     = *(const float4*)(&As[kk][ty * 4]);
            *(float4*)(a + 4) = *(const float4*)(&As[kk][ty * 4 + 64]);
            *(float4*)(bf)     = *(const float4*)(&Bs[kk][tx * 4]);
            *(float4*)(bf + 4) = *(const float4*)(&Bs[kk][tx * 4 + 64]);
            #pragma unroll
            for (int i = 0; i < 8; i++)
                #pragma unroll
                for (int j = 0; j < 8; j++) acc[i][j] += a[i] * bf[j];
        }
        __syncthreads();
    }

    #pragma unroll
    for (int i = 0; i < 8; i++) {
        int m = m0 + ty * 4 + ((i < 4) ? i : (64 + i - 4));
        float bv = bias[m];
        float4 v0 = make_float4(acc[i][0] + bv, acc[i][1] + bv, acc[i][2] + bv, acc[i][3] + bv);
        float4 v1 = make_float4(acc[i][4] + bv, acc[i][5] + bv, acc[i][6] + bv, acc[i][7] + bv);
        *(float4*)(Yb + (size_t)m * N + n0 + tx * 4)      = v0;
        *(float4*)(Yb + (size_t)m * N + n0 + 64 + tx * 4) = v1;
    }
}

// ---------------- GEMM 2: raw_attn  R[b][m][n] = sum_k F[b][k][m] * G[b][k][n]
// Both operands K-major (TN). M=N=4096, K=512.
__global__ __launch_bounds__(256) void gemm_attn(
    const float* __restrict__ F, const float* __restrict__ G,
    float* __restrict__ R, int M, int N, int K)
{
    int b = blockIdx.z;
    const float* Fb = F + (size_t)b * K * M;
    const float* Gb = G + (size_t)b * K * N;
    float* Rb = R + (size_t)b * M * N;
    int n0 = blockIdx.x * 128;
    int m0 = blockIdx.y * 128;

    __shared__ float As[BK][128];
    __shared__ float Bs[BK][128];

    int tid = threadIdx.x;
    int l_row = tid >> 5;            // k 0..7
    int l_col = (tid & 31) * 4;      // 0..124
    int ty = tid >> 4, tx = tid & 15;

    float acc[8][8];
    #pragma unroll
    for (int i = 0; i < 8; i++)
        #pragma unroll
        for (int j = 0; j < 8; j++) acc[i][j] = 0.f;

    for (int k0 = 0; k0 < K; k0 += BK) {
        *(float4*)(&As[l_row][l_col]) =
            *(const float4*)(Fb + (size_t)(k0 + l_row) * M + m0 + l_col);
        *(float4*)(&Bs[l_row][l_col]) =
            *(const float4*)(Gb + (size_t)(k0 + l_row) * N + n0 + l_col);
        __syncthreads();
        #pragma unroll
        for (int kk = 0; kk < BK; kk++) {
            float a[8], bf[8];
            *(float4*)(a)     = *(const float4*)(&As[kk][ty * 4]);
            *(float4*)(a + 4) = *(const float4*)(&As[kk][ty * 4 + 64]);
            *(float4*)(bf)     = *(const float4*)(&Bs[kk][tx * 4]);
            *(float4*)(bf + 4) = *(const float4*)(&Bs[kk][tx * 4 + 64]);
            #pragma unroll
            for (int i = 0; i < 8; i++)
                #pragma unroll
                for (int j = 0; j < 8; j++) acc[i][j] += a[i] * bf[j];
        }
        __syncthreads();
    }

    #pragma unroll
    for (int i = 0; i < 8; i++) {
        int m = m0 + ty * 4 + ((i < 4) ? i : (64 + i - 4));
        *(float4*)(Rb + (size_t)m * N + n0 + tx * 4)      = *(float4*)(&acc[i][0]);
        *(float4*)(Rb + (size_t)m * N + n0 + 64 + tx * 4) = *(float4*)(&acc[i][4]);
    }
}

// ---------------- softmax mix: per row of attn[b*4096+n][4096]
// S = softmax( w0*softmax(raw) + w1*softmax(relu(raw)) ), in place.
__global__ __launch_bounds__(256) void softmax_mix_kernel(
    float* __restrict__ attn, const float* __restrict__ w_mix)
{
    __shared__ float row[4096];
    __shared__ float red[32];
    float* p = attn + (size_t)blockIdx.x * 4096;
    int tid = threadIdx.x;

    float lmax = -1e30f;
    for (int i = tid; i < 4096; i += 256) {
        float v = p[i];
        row[i] = v;
        lmax = fmaxf(lmax, v);
    }
    float m1 = block_reduce_max(lmax, red);
    float m2 = fmaxf(m1, 0.f);

    float z1 = 0.f, z2 = 0.f;
    for (int i = tid; i < 4096; i += 256) {
        float v = row[i];
        z1 += expf(v - m1);
        z2 += expf(fmaxf(v, 0.f) - m2);
    }
    float Z1 = block_reduce_sum(z1, red);
    float Z2 = block_reduce_sum(z2, red);

    float e0 = expf(w_mix[0]), e1 = expf(w_mix[1]);
    float inv = 1.f / (e0 + e1);
    float iz1 = (e0 * inv) / Z1;
    float iz2 = (e1 * inv) / Z2;

    float za = 0.f;
    for (int i = tid; i < 4096; i += 256) {
        float v = row[i];
        float A = expf(v - m1) * iz1 + expf(fmaxf(v, 0.f) - m2) * iz2;
        float e = expf(A);     // A in (0,1]: safe without max-subtract
        row[i] = e;
        za += e;
    }
    float ZA = block_reduce_sum(za, red);
    float izA = 1.f / ZA;
    for (int i = tid; i < 4096; i += 256) p[i] = row[i] * izA;
}

// ---------------- GEMM 3: mean/second (dual accumulator, NT)
// mean[n][c] = sum_m S[n][m] * H[c][m]; second with H^2.
// Writes meanT[b][c][n], stdT[b][c][n] with std = sqrt(relu(second - mean^2)).
// Tile 128(n) x 64(c) x BK, 256 threads, micro 8(n) x 4(c).
__global__ __launch_bounds__(256) void gemm_meansec(
    const float* __restrict__ S, const float* __restrict__ H,
    float* __restrict__ meanT, float* __restrict__ stdT)
{
    int b = blockIdx.z;
    const float* Sb = S + (size_t)b * 4096ull * 4096ull;
    const float* Hb = H + (size_t)b * 512ull * 4096ull;
    float* mT = meanT + (size_t)b * 512ull * 4096ull;
    float* sT = stdT  + (size_t)b * 512ull * 4096ull;
    int n0 = blockIdx.x * 128;
    int c0 = blockIdx.y * 64;

    __shared__ float As[BK][128];   // [k][n]
    __shared__ float Bs[BK][64];    // [k][c]

    int tid = threadIdx.x;
    int a_row = tid >> 1;           // n 0..127
    int a_col = (tid & 1) * 4;      // k 0 or 4
    int ty = tid >> 4, tx = tid & 15;

    float am[8][4], a2[8][4];
    #pragma unroll
    for (int i = 0; i < 8; i++)
        #pragma unroll
        for (int j = 0; j < 4; j++) { am[i][j] = 0.f; a2[i][j] = 0.f; }

    for (int k0 = 0; k0 < 4096; k0 += BK) {
        float4 av = *(const float4*)(Sb + (size_t)(n0 + a_row) * 4096 + k0 + a_col);
        As[a_col + 0][a_row] = av.x;
        As[a_col + 1][a_row] = av.y;
        As[a_col + 2][a_row] = av.z;
        As[a_col + 3][a_row] = av.w;
        if (tid < 128) {
            int h_row = tid >> 1;          // c 0..63
            int h_col = (tid & 1) * 4;     // k 0 or 4
            float4 hv = *(const float4*)(Hb + (size_t)(c0 + h_row) * 4096 + k0 + h_col);
            Bs[h_col + 0][h_row] = hv.x;
            Bs[h_col + 1][h_row] = hv.y;
            Bs[h_col + 2][h_row] = hv.z;
            Bs[h_col + 3][h_row] = hv.w;
        }
        __syncthreads();
        #pragma unroll
        for (int kk = 0; kk < BK; kk++) {
            float a[8], bf[4], b2[4];
            *(float4*)(a)     = *(const float4*)(&As[kk][ty * 4]);
            *(float4*)(a + 4) = *(const float4*)(&As[kk][ty * 4 + 64]);
            *(float4*)(bf)    = *(const float4*)(&Bs[kk][tx * 4]);
            #pragma unroll
            for (int j = 0; j < 4; j++) b2[j] = bf[j] * bf[j];
            #pragma unroll
            for (int i = 0; i < 8; i++)
                #pragma unroll
                for (int j = 0; j < 4; j++) {
                    am[i][j] += a[i] * bf[j];
                    a2[i][j] += a[i] * b2[j];
                }
        }
        __syncthreads();
    }

    #pragma unroll
    for (int i = 0; i < 8; i++) {
        int n = n0 + ty * 4 + ((i < 4) ? i : (64 + i - 4));
        #pragma unroll
        for (int j = 0; j < 4; j++) {
            int c = c0 + tx * 4 + j;
            float m = am[i][j];
            float sd = sqrtf(fmaxf(a2[i][j] - m * m, 0.f));
            mT[(size_t)c * 4096 + n] = m;
            sT[(size_t)c * 4096 + n] = sd;
        }
    }
}

// ---------------- finalize: out = stdT * mvn(content) + meanT, per (b,c) row
__global__ __launch_bounds__(256) void finalize_kernel(
    const float* __restrict__ content, const float* __restrict__ meanT,
    const float* __restrict__ stdT, float* __restrict__ out)
{
    __shared__ float red[32];
    int c = blockIdx.x, b = blockIdx.y;
    size_t off = ((size_t)b * 512 + c) * 4096;
    const float* x = content + off;
    int tid = threadIdx.x;

    float s = 0.f, ss = 0.f;
    for (int i = tid; i < 4096; i += 256) {
        float v = x[i];
        s += v; ss += v * v;
    }
    s = block_reduce_sum(s, red);
    ss = block_reduce_sum(ss, red);
    float mu = s * (1.f / 4096.f);
    float var = (ss - 4096.f * mu * mu) * (1.f / 4095.f);   // ddof=1
    float rstd = rsqrtf(var + 1e-5f);

    for (int i = tid; i < 4096; i += 256) {
        out[off + i] = stdT[off + i] * ((x[i] - mu) * rstd) + meanT[off + i];
    }
}

// ---------------- launch ----------------
extern "C" void kernel_launch(void* const* d_in, const int* in_sizes, int n_in,
                              void* d_out, int out_size)
{
    const float* content     = (const float*)d_in[0];
    const float* style       = (const float*)d_in[1];
    const float* content_key = (const float*)d_in[2];
    const float* style_key   = (const float*)d_in[3];
    const float* f_w = (const float*)d_in[4];
    const float* f_b = (const float*)d_in[5];
    const float* g_w = (const float*)d_in[6];
    const float* g_b = (const float*)d_in[7];
    const float* h_w = (const float*)d_in[8];
    const float* h_b = (const float*)d_in[9];
    const float* w_mix = (const float*)d_in[10];
    float* out = (float*)d_out;

    float *Fm, *Gm, *Hm, *attn, *meanT, *stdT;
    cudaGetSymbolAddress((void**)&Fm, g_Fm);
    cudaGetSymbolAddress((void**)&Gm, g_Gm);
    cudaGetSymbolAddress((void**)&Hm, g_Hm);
    cudaGetSymbolAddress((void**)&attn, g_attn);
    cudaGetSymbolAddress((void**)&meanT, g_meanT);
    cudaGetSymbolAddress((void**)&stdT, g_stdT);

    // conv1x1 for F (content_key), G (style_key), H (style)
    gemm_conv<<<dim3(32, 4, 4), 256>>>(f_w, content_key, f_b, Fm, 512, 4096, 512);
    gemm_conv<<<dim3(32, 4, 4), 256>>>(g_w, style_key,   g_b, Gm, 512, 4096, 512);
    gemm_conv<<<dim3(32, 4, 4), 256>>>(h_w, style,       h_b, Hm, 512, 4096, 512);

    // raw attention
    gemm_attn<<<dim3(32, 32, 4), 256>>>(Fm, Gm, attn, 4096, 4096, 512);

    // fused triple-softmax mix (in place)
    softmax_mix_kernel<<<16384, 256>>>(attn, w_mix);

    // mean / second (dual) -> meanT, stdT in [b][c][n]
    gemm_meansec<<<dim3(32, 8, 4), 256>>>(attn, Hm, meanT, stdT);

    // final: std * mvn(content) + mean
    finalize_kernel<<<dim3(512, 4), 256>>>(content, meanT, stdT, out);
}

// round 3
// speedup vs baseline: 3.1147x; 3.1147x over previous
#include <cuda_runtime.h>
#include <math.h>
#include <stdint.h>

// ---------------- scratch (no allocations allowed) ----------------
__device__ float g_attn[4ull * 4096ull * 4096ull];   // also holds XT inputs pre-attn
__device__ float g_FmT[4u * 4096u * 512u];
__device__ float g_GmT[4u * 4096u * 512u];
__device__ float g_HmT[4u * 4096u * 512u];
__device__ float g_Hcat[4ull * 1024ull * 4096ull];   // [Hm ; Hm^2], k-major
__device__ float g_Ccat[4ull * 4096ull * 1024ull];   // mean|second, [n][c]
__device__ float g_meanT[4u * 512u * 4096u];
__device__ float g_stdT [4u * 512u * 4096u];

__device__ __forceinline__ uint32_t smem_u32(const void* p) {
    uint32_t a;
    asm("{ .reg .u64 t; cvta.to.shared.u64 t, %1; cvt.u32.u64 %0, t; }" : "=r"(a) : "l"(p));
    return a;
}
__device__ __forceinline__ void cp16(uint32_t dst, const void* src) {
    asm volatile("cp.async.ca.shared.global [%0], [%1], 16;" :: "r"(dst), "l"(src));
}

// ---------------- tf32 mma.sync GEMM ----------------
// C[b][m][n] = sum_k A[b][m][k] * B[b][n][k]  (+ bias[n])
// Block 128x128x32, 8 warps, warp tile 64x32 (m16n8k8 fragments).
// smem: A,B tiles stored [row][k] with row stride 36 floats (conflict-free frags).
template<int HAS_BIAS>
__global__ __launch_bounds__(256) void mma_gemm(
    const float* __restrict__ A, const float* __restrict__ B,
    const float* __restrict__ bias, float* __restrict__ C,
    int M, int N, int K, size_t sA, size_t sB)
{
    extern __shared__ float sm[];
    const int tid = threadIdx.x, lane = tid & 31, wid = tid >> 5;
    const int b = blockIdx.z;
    const int n0 = blockIdx.x * 128, m0 = blockIdx.y * 128;
    const float* Ag = A + (size_t)b * sA + (size_t)m0 * K;
    const float* Bg = B + (size_t)b * sB + (size_t)n0 * K;

    const uint32_t s_base = smem_u32(sm);
    // byte layout: A buffers [2][128*144], then B buffers [2][128*144]
    const int wm = (wid >> 2) * 64;      // 0 / 64
    const int wn = (wid & 3) * 32;       // 0,32,64,96

    float acc[4][4][4];
    #pragma unroll
    for (int i = 0; i < 4; i++)
        #pragma unroll
        for (int j = 0; j < 4; j++)
            #pragma unroll
            for (int r = 0; r < 4; r++) acc[i][j][r] = 0.f;

    const int NC = K / 32;

    // stage chunk ch into buffer buf
    auto stage = [&](int ch, int buf) {
        const float* Asrc = Ag + ch * 32;
        const float* Bsrc = Bg + ch * 32;
        uint32_t abase = s_base + buf * 18432u;
        uint32_t bbase = s_base + 36864u + buf * 18432u;
        #pragma unroll
        for (int it = 0; it < 4; it++) {
            int idx = tid + it * 256;
            int r = idx >> 3, f = idx & 7;
            cp16(abase + r * 144 + f * 16, Asrc + (size_t)r * K + f * 4);
            cp16(bbase + r * 144 + f * 16, Bsrc + (size_t)r * K + f * 4);
        }
        asm volatile("cp.async.commit_group;" ::: "memory");
    };

    stage(0, 0);
    for (int ch = 0; ch < NC; ch++) {
        const int buf = ch & 1;
        if (ch + 1 < NC) {
            stage(ch + 1, buf ^ 1);
            asm volatile("cp.async.wait_group 1;" ::: "memory");
        } else {
            asm volatile("cp.async.wait_group 0;" ::: "memory");
        }
        __syncthreads();

        const float* Ab = sm + buf * 4608;          // 18432 B
        const float* Bb = sm + 9216 + buf * 4608;

        #pragma unroll
        for (int k8 = 0; k8 < 32; k8 += 8) {
            uint32_t af[4][4], bf[4][2];
            const int kk = k8 + (lane & 3);
            #pragma unroll
            for (int im = 0; im < 4; im++) {
                int r = wm + im * 16 + (lane >> 2);
                af[im][0] = __float_as_uint(Ab[r * 36 + kk]);
                af[im][1] = __float_as_uint(Ab[(r + 8) * 36 + kk]);
                af[im][2] = __float_as_uint(Ab[r * 36 + kk + 4]);
                af[im][3] = __float_as_uint(Ab[(r + 8) * 36 + kk + 4]);
            }
            #pragma unroll
            for (int jn = 0; jn < 4; jn++) {
                int c = wn + jn * 8 + (lane >> 2);
                bf[jn][0] = __float_as_uint(Bb[c * 36 + kk]);
                bf[jn][1] = __float_as_uint(Bb[c * 36 + kk + 4]);
            }
            #pragma unroll
            for (int im = 0; im < 4; im++)
                #pragma unroll
                for (int jn = 0; jn < 4; jn++)
                    asm volatile(
                        "mma.sync.aligned.m16n8k8.row.col.f32.tf32.tf32.f32 "
                        "{%0,%1,%2,%3}, {%4,%5,%6,%7}, {%8,%9}, {%0,%1,%2,%3};"
                        : "+f"(acc[im][jn][0]), "+f"(acc[im][jn][1]),
                          "+f"(acc[im][jn][2]), "+f"(acc[im][jn][3])
                        : "r"(af[im][0]), "r"(af[im][1]), "r"(af[im][2]), "r"(af[im][3]),
                          "r"(bf[jn][0]), "r"(bf[jn][1]));
        }
        __syncthreads();
    }

    // epilogue: direct float2 stores (c0,c1)->(row,col), (c2,c3)->(row+8,col)
    float* Cb = C + (size_t)b * (size_t)M * (size_t)N;
    #pragma unroll
    for (int im = 0; im < 4; im++) {
        int r = m0 + wm + im * 16 + (lane >> 2);
        #pragma unroll
        for (int jn = 0; jn < 4; jn++) {
            int cc = n0 + wn + jn * 8 + (lane & 3) * 2;
            float b0 = 0.f, b1 = 0.f;
            if (HAS_BIAS) { b0 = __ldg(&bias[cc]); b1 = __ldg(&bias[cc + 1]); }
            *(float2*)(Cb + (size_t)r * N + cc) =
                make_float2(acc[im][jn][0] + b0, acc[im][jn][1] + b1);
            *(float2*)(Cb + (size_t)(r + 8) * N + cc) =
                make_float2(acc[im][jn][2] + b0, acc[im][jn][3] + b1);
        }
    }
}

// ---------------- transpose: src[b][R][C] -> dst[b][C][R] ----------------
__global__ void transpose_k(const float* __restrict__ src, float* __restrict__ dst, int R, int C)
{
    __shared__ float t[32][33];
    int b = blockIdx.z;
    const float* s = src + (size_t)b * R * C;
    float* d = dst + (size_t)b * R * C;
    int c0 = blockIdx.x * 32, r0 = blockIdx.y * 32;
    int tx = threadIdx.x, ty = threadIdx.y;
    #pragma unroll
    for (int k = 0; k < 4; k++)
        t[ty + k * 8][tx] = s[(size_t)(r0 + ty + k * 8) * C + c0 + tx];
    __syncthreads();
    #pragma unroll
    for (int k = 0; k < 4; k++)
        d[(size_t)(c0 + ty + k * 8) * R + r0 + tx] = t[tx][ty + k * 8];
}

// HmT [b][4096][512] -> Hcat [b][1024][4096]: rows 0..511 = Hm[c][n], 512..1023 = Hm^2
__global__ void transpose_sq(const float* __restrict__ src, float* __restrict__ dst)
{
    __shared__ float t[32][33];
    int b = blockIdx.z;
    const float* s = src + (size_t)b * 4096ull * 512ull;
    float* d = dst + (size_t)b * 1024ull * 4096ull;
    int c0 = blockIdx.x * 32, r0 = blockIdx.y * 32;
    int tx = threadIdx.x, ty = threadIdx.y;
    #pragma unroll
    for (int k = 0; k < 4; k++)
        t[ty + k * 8][tx] = s[(size_t)(r0 + ty + k * 8) * 512 + c0 + tx];
    __syncthreads();
    #pragma unroll
    for (int k = 0; k < 4; k++) {
        float v = t[tx][ty + k * 8];
        d[(size_t)(c0 + ty + k * 8) * 4096 + r0 + tx] = v;
        d[(size_t)(512 + c0 + ty + k * 8) * 4096 + r0 + tx] = v * v;
    }
}

// Ccat [b][n][1024] -> meanT/stdT [b][c][n]
__global__ void meanstd_transpose(const float* __restrict__ Ccat,
                                  float* __restrict__ meanT, float* __restrict__ stdT)
{
    __shared__ float tm[32][33], ts[32][33];
    int b = blockIdx.z;
    int c0 = blockIdx.x * 32, n0 = blockIdx.y * 32;
    const float* Cb = Ccat + (size_t)b * 4096ull * 1024ull;
    int tx = threadIdx.x, ty = threadIdx.y;
    #pragma unroll
    for (int k = 0; k < 4; k++) {
        int n = n0 + ty + k * 8;
        float mn = Cb[(size_t)n * 1024 + c0 + tx];
        float sc = Cb[(size_t)n * 1024 + 512 + c0 + tx];
        tm[ty + k * 8][tx] = mn;
        ts[ty + k * 8][tx] = sqrtf(fmaxf(sc - mn * mn, 0.f));
    }
    __syncthreads();
    size_t ob = (size_t)b * 512ull * 4096ull;
    #pragma unroll
    for (int k = 0; k < 4; k++) {
        int c = c0 + ty + k * 8;
        meanT[ob + (size_t)c * 4096 + n0 + tx] = tm[tx][ty + k * 8];
        stdT [ob + (size_t)c * 4096 + n0 + tx] = ts[tx][ty + k * 8];
    }
}

// ---------------- block reductions ----------------
__device__ __forceinline__ float block_reduce_max(float v, float* red) {
    #pragma unroll
    for (int o = 16; o > 0; o >>= 1) v = fmaxf(v, __shfl_xor_sync(0xffffffffu, v, o));
    int wid = threadIdx.x >> 5, lid = threadIdx.x & 31;
    if (lid == 0) red[wid] = v;
    __syncthreads();
    if (wid == 0) {
        v = (lid < 8) ? red[lid] : -1e30f;
        #pragma unroll
        for (int o = 4; o > 0; o >>= 1) v = fmaxf(v, __shfl_xor_sync(0xffffffffu, v, o));
        if (lid == 0) red[0] = v;
    }
    __syncthreads();
    float r = red[0];
    __syncthreads();
    return r;
}
__device__ __forceinline__ float block_reduce_sum(float v, float* red) {
    #pragma unroll
    for (int o = 16; o > 0; o >>= 1) v += __shfl_xor_sync(0xffffffffu, v, o);
    int wid = threadIdx.x >> 5, lid = threadIdx.x & 31;
    if (lid == 0) red[wid] = v;
    __syncthreads();
    if (wid == 0) {
        v = (lid < 8) ? red[lid] : 0.f;
        #pragma unroll
        for (int o = 4; o > 0; o >>= 1) v += __shfl_xor_sync(0xffffffffu, v, o);
        if (lid == 0) red[0] = v;
    }
    __syncthreads();
    float r = red[0];
    __syncthreads();
    return r;
}

// ---------------- softmax mix (per attn row, in place) ----------------
__global__ __launch_bounds__(256) void softmax_mix_kernel(
    float* __restrict__ attn, const float* __restrict__ w_mix)
{
    __shared__ float row[4096];
    __shared__ float red[32];
    float* p = attn + (size_t)blockIdx.x * 4096;
    int tid = threadIdx.x;

    float lmax = -1e30f;
    for (int i = tid; i < 4096; i += 256) {
        float v = p[i];
        row[i] = v;
        lmax = fmaxf(lmax, v);
    }
    float m1 = block_reduce_max(lmax, red);
    float m2 = fmaxf(m1, 0.f);

    float z1 = 0.f, z2 = 0.f;
    for (int i = tid; i < 4096; i += 256) {
        float v = row[i];
        z1 += expf(v - m1);
        z2 += expf(fmaxf(v, 0.f) - m2);
    }
    float Z1 = block_reduce_sum(z1, red);
    float Z2 = block_reduce_sum(z2, red);

    float e0 = expf(w_mix[0]), e1 = expf(w_mix[1]);
    float inv = 1.f / (e0 + e1);
    float iz1 = (e0 * inv) / Z1;
    float iz2 = (e1 * inv) / Z2;

    float za = 0.f;
    for (int i = tid; i < 4096; i += 256) {
        float v = row[i];
        float A = expf(v - m1) * iz1 + expf(fmaxf(v, 0.f) - m2) * iz2;
        float e = expf(A);   // A in (0,1]
        row[i] = e;
        za += e;
    }
    float ZA = block_reduce_sum(za, red);
    float izA = 1.f / ZA;
    for (int i = tid; i < 4096; i += 256) p[i] = row[i] * izA;
}

// ---------------- finalize: out = stdT * mvn(content) + meanT ----------------
__global__ __launch_bounds__(256) void finalize_kernel(
    const float* __restrict__ content, const float* __restrict__ meanT,
    const float* __restrict__ stdT, float* __restrict__ out)
{
    __shared__ float red[32];
    int c = blockIdx.x, b = blockIdx.y;
    size_t off = ((size_t)b * 512 + c) * 4096;
    const float* x = content + off;
    int tid = threadIdx.x;

    float s = 0.f, ss = 0.f;
    for (int i = tid; i < 4096; i += 256) {
        float v = x[i];
        s += v; ss += v * v;
    }
    s = block_reduce_sum(s, red);
    ss = block_reduce_sum(ss, red);
    float mu = s * (1.f / 4096.f);
    float var = (ss - 4096.f * mu * mu) * (1.f / 4095.f);
    float rstd = rsqrtf(var + 1e-5f);

    for (int i = tid; i < 4096; i += 256)
        out[off + i] = stdT[off + i] * ((x[i] - mu) * rstd) + meanT[off + i];
}

// ---------------- launch ----------------
extern "C" void kernel_launch(void* const* d_in, const int* in_sizes, int n_in,
                              void* d_out, int out_size)
{
    const float* content     = (const float*)d_in[0];
    const float* style       = (const float*)d_in[1];
    const float* content_key = (const float*)d_in[2];
    const float* style_key   = (const float*)d_in[3];
    const float* f_w = (const float*)d_in[4];
    const float* f_b = (const float*)d_in[5];
    const float* g_w = (const float*)d_in[6];
    const float* g_b = (const float*)d_in[7];
    const float* h_w = (const float*)d_in[8];
    const float* h_b = (const float*)d_in[9];
    const float* w_mix = (const float*)d_in[10];
    float* out = (float*)d_out;

    float *attn, *FmT, *GmT, *HmT, *Hcat, *Ccat, *meanT, *stdT;
    cudaGetSymbolAddress((void**)&attn,  g_attn);
    cudaGetSymbolAddress((void**)&FmT,   g_FmT);
    cudaGetSymbolAddress((void**)&GmT,   g_GmT);
    cudaGetSymbolAddress((void**)&HmT,   g_HmT);
    cudaGetSymbolAddress((void**)&Hcat,  g_Hcat);
    cudaGetSymbolAddress((void**)&Ccat,  g_Ccat);
    cudaGetSymbolAddress((void**)&meanT, g_meanT);
    cudaGetSymbolAddress((void**)&stdT,  g_stdT);

    const int SMEM = 4 * 128 * 144;   // 73728 B: A,B double-buffered (stride 36)
    cudaFuncSetAttribute(mma_gemm<1>, cudaFuncAttributeMaxDynamicSharedMemorySize, SMEM);
    cudaFuncSetAttribute(mma_gemm<0>, cudaFuncAttributeMaxDynamicSharedMemorySize, SMEM);

    // XT scratch lives in the (not-yet-used) attn buffer
    float* XT0 = attn;
    float* XT1 = attn + 8388608;     // 4*4096*512
    float* XT2 = attn + 16777216;

    // 1) transpose inputs [b][512][4096] -> [b][4096][512]
    transpose_k<<<dim3(128, 16, 4), dim3(32, 8)>>>(content_key, XT0, 512, 4096);
    transpose_k<<<dim3(128, 16, 4), dim3(32, 8)>>>(style_key,   XT1, 512, 4096);
    transpose_k<<<dim3(128, 16, 4), dim3(32, 8)>>>(style,       XT2, 512, 4096);

    // 2) convs: FmT[n][o] = sum_c XT[n][c] * W[o][c] + b[o]
    mma_gemm<1><<<dim3(4, 32, 4), 256, SMEM>>>(XT0, f_w, f_b, FmT,
        4096, 512, 512, (size_t)4096 * 512, 0);
    mma_gemm<1><<<dim3(4, 32, 4), 256, SMEM>>>(XT1, g_w, g_b, GmT,
        4096, 512, 512, (size_t)4096 * 512, 0);
    mma_gemm<1><<<dim3(4, 32, 4), 256, SMEM>>>(XT2, h_w, h_b, HmT,
        4096, 512, 512, (size_t)4096 * 512, 0);

    // 3) Hcat[b][1024][4096] = [Hm[c][n] ; Hm[c][n]^2]
    transpose_sq<<<dim3(16, 128, 4), dim3(32, 8)>>>(HmT, Hcat);

    // 4) raw attention: attn[nc][ns] = sum_ck FmT[nc][ck] * GmT[ns][ck]
    mma_gemm<0><<<dim3(32, 32, 4), 256, SMEM>>>(FmT, GmT, nullptr, attn,
        4096, 4096, 512, (size_t)4096 * 512, (size_t)4096 * 512);

    // 5) triple-softmax mix, in place
    softmax_mix_kernel<<<16384, 256>>>(attn, w_mix);

    // 6) mean/second GEMM vs Hcat -> Ccat[b][n][1024]
    mma_gemm<0><<<dim3(8, 32, 4), 256, SMEM>>>(attn, Hcat, nullptr, Ccat,
        4096, 1024, 4096, (size_t)4096 * 4096, (size_t)1024 * 4096);

    // 7) Ccat -> meanT/stdT [b][c][n]
    meanstd_transpose<<<dim3(16, 128, 4), dim3(32, 8)>>>(Ccat, meanT, stdT);

    // 8) finalize
    finalize_kernel<<<dim3(512, 4), 256>>>(content, meanT, stdT, out);
}